// round 3
// baseline (speedup 1.0000x reference)
#include <cuda_runtime.h>

#define N_NODES 10000
#define N_EDGES 320000
#define ETOT    330000
#define H       128
#define F_IN    256
#define NEG_SLOPE 0.2f

// ---------------- scratch ----------------------------------------------------
__device__ float g_h  [N_NODES * H];   // GEMM output (pre-aggregation h)
__device__ float g_hn [N_NODES * H];   // post-GAT relu output (layer-2 input)
__device__ float g_as [N_NODES];
__device__ float g_ad [N_NODES];
__device__ int   g_cnt[N_NODES];
__device__ int   g_off[N_NODES + 1];
__device__ int   g_rank[ETOT];         // edge rank within its dst bucket
__device__ int   g_psrc[ETOT];         // src node per CSR slot
__device__ float g_acc2[2];
__device__ int   g_done;               // completion counter (self-resetting)

// ---------------- init -------------------------------------------------------
__global__ void k_init() {
    int i = blockIdx.x * blockDim.x + threadIdx.x;
    if (i < N_NODES) g_cnt[i] = 0;
    if (i < 2) g_acc2[i] = 0.0f;
}

// ---------------- histogram + per-edge rank, 4 edges/thread ------------------
__global__ void k_hist(const int* __restrict__ ei) {
    int i = (blockIdx.x * blockDim.x + threadIdx.x) * 4;
    if (i >= ETOT) return;
    if (i < N_EDGES) {                       // N_EDGES % 4 == 0: pure edge block
        int4 d4 = *(const int4*)(ei + N_EDGES + i);
        int4 r4;
        r4.x = atomicAdd(&g_cnt[d4.x], 1);
        r4.y = atomicAdd(&g_cnt[d4.y], 1);
        r4.z = atomicAdd(&g_cnt[d4.z], 1);
        r4.w = atomicAdd(&g_cnt[d4.w], 1);
        *(int4*)(g_rank + i) = r4;
    } else {                                  // self loops
        int4 r4;
        int d = i - N_EDGES;
        r4.x = atomicAdd(&g_cnt[d + 0], 1);
        r4.y = atomicAdd(&g_cnt[d + 1], 1);
        r4.z = atomicAdd(&g_cnt[d + 2], 1);
        r4.w = atomicAdd(&g_cnt[d + 3], 1);
        *(int4*)(g_rank + i) = r4;
    }
}

__global__ void k_scan() {   // single block, 1024 threads
    __shared__ int sd[1024];
    const int CH = (N_NODES + 1023) / 1024;   // 10
    int t = threadIdx.x;
    int base = t * CH;
    int local[CH];
    int sum = 0;
    #pragma unroll
    for (int k = 0; k < CH; k++) {
        int i = base + k;
        int c = (i < N_NODES) ? g_cnt[i] : 0;
        local[k] = sum;
        sum += c;
    }
    sd[t] = sum;
    __syncthreads();
    for (int o = 1; o < 1024; o <<= 1) {
        int v = (t >= o) ? sd[t - o] : 0;
        __syncthreads();
        sd[t] += v;
        __syncthreads();
    }
    int excl = sd[t] - sum;
    #pragma unroll
    for (int k = 0; k < CH; k++) {
        int i = base + k;
        if (i < N_NODES) g_off[i] = excl + local[k];
    }
    if (t == 0) g_off[N_NODES] = ETOT;
}

// placement: no atomics, 4 edges/thread
__global__ void k_place(const int* __restrict__ ei) {
    int i = (blockIdx.x * blockDim.x + threadIdx.x) * 4;
    if (i >= ETOT) return;
    int4 r4 = *(const int4*)(g_rank + i);
    if (i < N_EDGES) {
        int4 s4 = *(const int4*)(ei + i);
        int4 d4 = *(const int4*)(ei + N_EDGES + i);
        int o0 = g_off[d4.x], o1 = g_off[d4.y], o2 = g_off[d4.z], o3 = g_off[d4.w];
        g_psrc[o0 + r4.x] = s4.x;
        g_psrc[o1 + r4.y] = s4.y;
        g_psrc[o2 + r4.z] = s4.z;
        g_psrc[o3 + r4.w] = s4.w;
    } else {
        int d = i - N_EDGES;
        int o0 = g_off[d + 0], o1 = g_off[d + 1], o2 = g_off[d + 2], o3 = g_off[d + 3];
        g_psrc[o0 + r4.x] = d + 0;
        g_psrc[o1 + r4.y] = d + 1;
        g_psrc[o2 + r4.z] = d + 2;
        g_psrc[o3 + r4.w] = d + 3;
    }
}

// ---------------- GEMM + fused attention dots --------------------------------
// g_h[M,128] = A[M,K] @ B[K,128]; also g_as[m]=h[m]·att_s, g_ad[m]=h[m]·att_d
// BM=64, BN=128, BK=16, 256 threads, 4x8 microtile, register double-buffer.
#define BM 64
#define BN 128
#define BK 16
__global__ __launch_bounds__(256, 2)
void k_gemm(const float* __restrict__ Ain, const float* __restrict__ B,
            const float* __restrict__ att_s, const float* __restrict__ att_d,
            int M, int K) {
    const float* A = Ain ? Ain : g_hn;   // layer 2 reads relu(h1)
    __shared__ float As[BK][BM];
    __shared__ float Bs[BK][BN];

    int tid = threadIdx.x;
    int tx  = tid & 15;    // 16 col groups of 8
    int ty  = tid >> 4;    // 16 row groups of 4
    int m0  = blockIdx.x * BM;

    // A tile: 64x16 = 256 float4, one per thread (row = tid>>2, col4 = (tid&3)*4)
    int ar = tid >> 2, ac = (tid & 3) << 2;
    // B tile: 16x128 = 512 float4, two per thread
    float4 aReg;
    float4 bReg0, bReg1;

    float acc[4][8];
    #pragma unroll
    for (int i = 0; i < 4; i++)
        #pragma unroll
        for (int j = 0; j < 8; j++) acc[i][j] = 0.0f;

    // prologue load
    {
        int gm = m0 + ar;
        aReg = (gm < M) ? *(const float4*)(A + (size_t)gm * K + ac)
                        : make_float4(0.f, 0.f, 0.f, 0.f);
        int q0 = tid * 2, q1 = tid * 2 + 1;
        bReg0 = *(const float4*)(B + (size_t)(q0 >> 5) * BN + ((q0 & 31) << 2));
        bReg1 = *(const float4*)(B + (size_t)(q1 >> 5) * BN + ((q1 & 31) << 2));
    }

    for (int k0 = 0; k0 < K; k0 += BK) {
        // store prefetched tile to smem
        As[ac + 0][ar] = aReg.x;
        As[ac + 1][ar] = aReg.y;
        As[ac + 2][ar] = aReg.z;
        As[ac + 3][ar] = aReg.w;
        {
            int q0 = tid * 2, q1 = tid * 2 + 1;
            *(float4*)&Bs[q0 >> 5][(q0 & 31) << 2] = bReg0;
            *(float4*)&Bs[q1 >> 5][(q1 & 31) << 2] = bReg1;
        }
        __syncthreads();

        // prefetch next tile into registers
        int kn = k0 + BK;
        if (kn < K) {
            int gm = m0 + ar;
            aReg = (gm < M) ? *(const float4*)(A + (size_t)gm * K + kn + ac)
                            : make_float4(0.f, 0.f, 0.f, 0.f);
            int q0 = tid * 2, q1 = tid * 2 + 1;
            bReg0 = *(const float4*)(B + (size_t)(kn + (q0 >> 5)) * BN + ((q0 & 31) << 2));
            bReg1 = *(const float4*)(B + (size_t)(kn + (q1 >> 5)) * BN + ((q1 & 31) << 2));
        }

        #pragma unroll
        for (int kk = 0; kk < BK; kk++) {
            float4 a  = *(const float4*)&As[kk][ty * 4];
            float4 b0 = *(const float4*)&Bs[kk][tx * 8];
            float4 b1 = *(const float4*)&Bs[kk][tx * 8 + 4];
            float av[4] = {a.x, a.y, a.z, a.w};
            float bv[8] = {b0.x, b0.y, b0.z, b0.w, b1.x, b1.y, b1.z, b1.w};
            #pragma unroll
            for (int i = 0; i < 4; i++)
                #pragma unroll
                for (int j = 0; j < 8; j++)
                    acc[i][j] += av[i] * bv[j];
        }
        __syncthreads();
    }

    // attention weights for this thread's 8 columns
    float asw[8], adw[8];
    #pragma unroll
    for (int j = 0; j < 8; j++) {
        asw[j] = att_s[tx * 8 + j];
        adw[j] = att_d[tx * 8 + j];
    }

    #pragma unroll
    for (int i = 0; i < 4; i++) {
        int gm = m0 + ty * 4 + i;
        float ps = 0.f, pd = 0.f;
        #pragma unroll
        for (int j = 0; j < 8; j++) {
            ps += acc[i][j] * asw[j];
            pd += acc[i][j] * adw[j];
        }
        // reduce over the 16 tx-threads (lane = (ty&1)*16 + tx)
        #pragma unroll
        for (int o = 8; o; o >>= 1) {
            ps += __shfl_down_sync(0xffffffffu, ps, o, 16);
            pd += __shfl_down_sync(0xffffffffu, pd, o, 16);
        }
        if (gm < M) {
            *(float4*)(g_h + (size_t)gm * BN + tx * 8) =
                make_float4(acc[i][0], acc[i][1], acc[i][2], acc[i][3]);
            *(float4*)(g_h + (size_t)gm * BN + tx * 8 + 4) =
                make_float4(acc[i][4], acc[i][5], acc[i][6], acc[i][7]);
            if (tx == 0) { g_as[gm] = ps; g_ad[gm] = pd; }
        }
    }
}

// ---------------- aggregation: warp per dst node, float4, unroll 4 -----------
// out[n][:] = relu( (Σ_e w_e h[src_e]) / (Σ_e w_e) + bias ),
// w_e = exp(leaky_relu(a_s[src] + a_d[n]))   (segment-max skipped: exp(e)/Σexp(e))
__device__ __forceinline__ float lrexp(float e) {
    e = e > 0.f ? e : NEG_SLOPE * e;
    return __expf(e);
}

template<bool TAIL>
__global__ void k_agg(const float* __restrict__ bias,
                      const float* __restrict__ Wr, const float* __restrict__ br,
                      const float* __restrict__ Wc, const float* __restrict__ bc,
                      float* __restrict__ out) {
    int warp = threadIdx.x >> 5;
    int lane = threadIdx.x & 31;
    int n = blockIdx.x * 4 + warp;
    __shared__ float s0s[4], s1s[4];

    int s = g_off[n], e = g_off[n + 1];
    float ad = g_ad[n];
    const float4* h4 = (const float4*)g_h;
    float4 acc = make_float4(0.f, 0.f, 0.f, 0.f);
    float z = 0.f;

    int p = s;
    for (; p + 4 <= e; p += 4) {
        int a0 = __ldg(&g_psrc[p]);
        int a1 = __ldg(&g_psrc[p + 1]);
        int a2 = __ldg(&g_psrc[p + 2]);
        int a3 = __ldg(&g_psrc[p + 3]);
        float w0 = lrexp(g_as[a0] + ad);
        float w1 = lrexp(g_as[a1] + ad);
        float w2 = lrexp(g_as[a2] + ad);
        float w3 = lrexp(g_as[a3] + ad);
        float4 h0 = h4[(size_t)a0 * 32 + lane];
        float4 h1 = h4[(size_t)a1 * 32 + lane];
        float4 h2 = h4[(size_t)a2 * 32 + lane];
        float4 h3 = h4[(size_t)a3 * 32 + lane];
        z += (w0 + w1) + (w2 + w3);
        acc.x += w0 * h0.x + w1 * h1.x + w2 * h2.x + w3 * h3.x;
        acc.y += w0 * h0.y + w1 * h1.y + w2 * h2.y + w3 * h3.y;
        acc.z += w0 * h0.z + w1 * h1.z + w2 * h2.z + w3 * h3.z;
        acc.w += w0 * h0.w + w1 * h1.w + w2 * h2.w + w3 * h3.w;
    }
    for (; p < e; p++) {
        int a0 = __ldg(&g_psrc[p]);
        float w0 = lrexp(g_as[a0] + ad);
        float4 h0 = h4[(size_t)a0 * 32 + lane];
        z += w0;
        acc.x += w0 * h0.x; acc.y += w0 * h0.y;
        acc.z += w0 * h0.z; acc.w += w0 * h0.w;
    }

    float inv = 1.0f / z;
    float4 b4 = ((const float4*)bias)[lane];
    float4 v;
    v.x = fmaxf(acc.x * inv + b4.x, 0.f);
    v.y = fmaxf(acc.y * inv + b4.y, 0.f);
    v.z = fmaxf(acc.z * inv + b4.z, 0.f);
    v.w = fmaxf(acc.w * inv + b4.w, 0.f);

    if (!TAIL) {
        ((float4*)g_hn)[(size_t)n * 32 + lane] = v;
    } else {
        // fused tail: r = v·Wr + br ; acc2 += r * Wc[n]; last block writes out
        float4 wr = ((const float4*)Wr)[lane];
        float dot = v.x * wr.x + v.y * wr.y + v.z * wr.z + v.w * wr.w;
        #pragma unroll
        for (int o = 16; o; o >>= 1) dot += __shfl_down_sync(0xffffffffu, dot, o);
        if (lane == 0) {
            float r = dot + br[0];
            s0s[warp] = r * Wc[n * 2 + 0];
            s1s[warp] = r * Wc[n * 2 + 1];
        }
        __syncthreads();
        if (threadIdx.x == 0) {
            atomicAdd(&g_acc2[0], s0s[0] + s0s[1] + s0s[2] + s0s[3]);
            atomicAdd(&g_acc2[1], s1s[0] + s1s[1] + s1s[2] + s1s[3]);
            __threadfence();
            int old = atomicAdd(&g_done, 1);
            if (old == gridDim.x - 1) {
                g_done = 0;  // reset for next graph replay
                float r0 = atomicAdd(&g_acc2[0], 0.0f);
                float r1 = atomicAdd(&g_acc2[1], 0.0f);
                out[0] = r0 + bc[0];
                out[1] = r1 + bc[1];
            }
        }
    }
}

// ---------------- launch -------------------------------------------------------
extern "C" void kernel_launch(void* const* d_in, const int* in_sizes, int n_in,
                              void* d_out, int out_size) {
    const float* x   = (const float*)d_in[0];
    const int*   ei  = (const int*)  d_in[1];
    const float* W1  = (const float*)d_in[2];
    const float* as1 = (const float*)d_in[3];
    const float* ad1 = (const float*)d_in[4];
    const float* b1  = (const float*)d_in[5];
    const float* W2  = (const float*)d_in[6];
    const float* as2 = (const float*)d_in[7];
    const float* ad2 = (const float*)d_in[8];
    const float* b2  = (const float*)d_in[9];
    const float* Wr  = (const float*)d_in[10];
    const float* br  = (const float*)d_in[11];
    const float* Wc  = (const float*)d_in[12];
    const float* bc  = (const float*)d_in[13];
    float* out = (float*)d_out;

    // CSR build
    k_init <<<(N_NODES + 255) / 256, 256>>>();
    k_hist <<<(ETOT / 4 + 255) / 256, 256>>>(ei);
    k_scan <<<1, 1024>>>();
    k_place<<<(ETOT / 4 + 255) / 256, 256>>>(ei);

    int gemm_grid = (N_NODES + BM - 1) / BM;

    // layer 1
    k_gemm<<<gemm_grid, 256>>>(x, W1, as1, ad1, N_NODES, F_IN);
    k_agg<false><<<N_NODES / 4, 128>>>(b1, nullptr, nullptr, nullptr, nullptr, nullptr);

    // layer 2 (+ fused tail and final output)
    k_gemm<<<gemm_grid, 256>>>(nullptr, W2, as2, ad2, N_NODES, H);
    k_agg<true><<<N_NODES / 4, 128>>>(b2, Wr, br, Wc, bc, out);
}

// round 5
// speedup vs baseline: 1.0884x; 1.0884x over previous
#include <cuda_runtime.h>
#include <cuda_fp16.h>

#define N_NODES 10000
#define N_EDGES 320000
#define ETOT    330000
#define H       128
#define F_IN    256
#define NEG_SLOPE 0.2f

// ---------------- scratch ----------------------------------------------------
__device__ __half g_h16[N_NODES * H];  // GEMM output, fp16 (gather-only consumer)
__device__ float  g_hn [N_NODES * H];  // post-GAT relu output (layer-2 input, fp32)
__device__ float  g_as [N_NODES];
__device__ float  g_ad [N_NODES];
__device__ int    g_cnt[N_NODES];
__device__ int    g_off[N_NODES + 1];
__device__ int    g_rank[ETOT];
__device__ int    g_psrc[ETOT];
__device__ float  g_acc2[2];
__device__ int    g_done;

// ---------------- init -------------------------------------------------------
__global__ void k_init() {
    int i = blockIdx.x * blockDim.x + threadIdx.x;
    if (i < N_NODES) g_cnt[i] = 0;
    if (i < 2) g_acc2[i] = 0.0f;
}

// ---------------- histogram + per-edge rank, 4 edges/thread ------------------
__global__ void k_hist(const int* __restrict__ ei) {
    int i = (blockIdx.x * blockDim.x + threadIdx.x) * 4;
    if (i >= ETOT) return;
    if (i < N_EDGES) {
        int4 d4 = *(const int4*)(ei + N_EDGES + i);
        int4 r4;
        r4.x = atomicAdd(&g_cnt[d4.x], 1);
        r4.y = atomicAdd(&g_cnt[d4.y], 1);
        r4.z = atomicAdd(&g_cnt[d4.z], 1);
        r4.w = atomicAdd(&g_cnt[d4.w], 1);
        *(int4*)(g_rank + i) = r4;
    } else {
        int4 r4;
        int d = i - N_EDGES;
        r4.x = atomicAdd(&g_cnt[d + 0], 1);
        r4.y = atomicAdd(&g_cnt[d + 1], 1);
        r4.z = atomicAdd(&g_cnt[d + 2], 1);
        r4.w = atomicAdd(&g_cnt[d + 3], 1);
        *(int4*)(g_rank + i) = r4;
    }
}

__global__ void k_scan() {   // single block, 1024 threads
    __shared__ int sd[1024];
    const int CH = (N_NODES + 1023) / 1024;   // 10
    int t = threadIdx.x;
    int base = t * CH;
    int local[CH];
    int sum = 0;
    #pragma unroll
    for (int k = 0; k < CH; k++) {
        int i = base + k;
        int c = (i < N_NODES) ? g_cnt[i] : 0;
        local[k] = sum;
        sum += c;
    }
    sd[t] = sum;
    __syncthreads();
    for (int o = 1; o < 1024; o <<= 1) {
        int v = (t >= o) ? sd[t - o] : 0;
        __syncthreads();
        sd[t] += v;
        __syncthreads();
    }
    int excl = sd[t] - sum;
    #pragma unroll
    for (int k = 0; k < CH; k++) {
        int i = base + k;
        if (i < N_NODES) g_off[i] = excl + local[k];
    }
    if (t == 0) g_off[N_NODES] = ETOT;
}

__global__ void k_place(const int* __restrict__ ei) {
    int i = (blockIdx.x * blockDim.x + threadIdx.x) * 4;
    if (i >= ETOT) return;
    int4 r4 = *(const int4*)(g_rank + i);
    if (i < N_EDGES) {
        int4 s4 = *(const int4*)(ei + i);
        int4 d4 = *(const int4*)(ei + N_EDGES + i);
        int o0 = g_off[d4.x], o1 = g_off[d4.y], o2 = g_off[d4.z], o3 = g_off[d4.w];
        g_psrc[o0 + r4.x] = s4.x;
        g_psrc[o1 + r4.y] = s4.y;
        g_psrc[o2 + r4.z] = s4.z;
        g_psrc[o3 + r4.w] = s4.w;
    } else {
        int d = i - N_EDGES;
        int o0 = g_off[d + 0], o1 = g_off[d + 1], o2 = g_off[d + 2], o3 = g_off[d + 3];
        g_psrc[o0 + r4.x] = d + 0;
        g_psrc[o1 + r4.y] = d + 1;
        g_psrc[o2 + r4.z] = d + 2;
        g_psrc[o3 + r4.w] = d + 3;
    }
}

// ---------------- GEMM + fused attention dots (R2 known-good mainloop) -------
// h[M,128] = A[M,K] @ B[K,128]; stores h as fp16; g_as/g_ad fp32 from registers.
// BM=64, BN=128, BK=16, 128 threads, 8x8 per-thread microtile.
#define BM 64
#define BN 128
#define BK 16
__global__ __launch_bounds__(128, 2)
void k_gemm(const float* __restrict__ Ain, const float* __restrict__ B,
            const float* __restrict__ att_s, const float* __restrict__ att_d,
            int M, int K) {
    const float* A = Ain ? Ain : g_hn;   // layer 2 reads relu(h1)
    __shared__ float As[BK][BM];
    __shared__ float Bs[BK][BN];

    int tid = threadIdx.x;
    int tx  = tid & 15;    // 16 col groups of 8
    int ty  = tid >> 4;    // 8 row groups of 8
    int m0  = blockIdx.x * BM;

    float acc[8][8];
    #pragma unroll
    for (int i = 0; i < 8; i++)
        #pragma unroll
        for (int j = 0; j < 8; j++) acc[i][j] = 0.0f;

    for (int k0 = 0; k0 < K; k0 += BK) {
        // A tile 64x16 (256 float4), 2 per thread, stored transposed
        #pragma unroll
        for (int t = 0; t < 2; t++) {
            int q   = tid * 2 + t;
            int r   = q >> 2;          // row in tile 0..63
            int c4  = (q & 3) << 2;    // col 0,4,8,12
            int gm  = m0 + r;
            float4 av = (gm < M) ? *(const float4*)(A + (size_t)gm * K + k0 + c4)
                                 : make_float4(0.f, 0.f, 0.f, 0.f);
            As[c4 + 0][r] = av.x;
            As[c4 + 1][r] = av.y;
            As[c4 + 2][r] = av.z;
            As[c4 + 3][r] = av.w;
        }
        // B tile 16x128 (512 float4), 4 per thread
        #pragma unroll
        for (int t = 0; t < 4; t++) {
            int q = tid * 4 + t;
            int r = q >> 5;            // row 0..15
            int c = (q & 31) << 2;     // col
            *(float4*)&Bs[r][c] = *(const float4*)(B + (size_t)(k0 + r) * BN + c);
        }
        __syncthreads();

        #pragma unroll
        for (int kk = 0; kk < BK; kk++) {
            float4 a0 = *(const float4*)&As[kk][ty * 8];
            float4 a1 = *(const float4*)&As[kk][ty * 8 + 4];
            float4 b0 = *(const float4*)&Bs[kk][tx * 8];
            float4 b1 = *(const float4*)&Bs[kk][tx * 8 + 4];
            float a[8] = {a0.x, a0.y, a0.z, a0.w, a1.x, a1.y, a1.z, a1.w};
            float b[8] = {b0.x, b0.y, b0.z, b0.w, b1.x, b1.y, b1.z, b1.w};
            #pragma unroll
            for (int i = 0; i < 8; i++)
                #pragma unroll
                for (int j = 0; j < 8; j++)
                    acc[i][j] += a[i] * b[j];
        }
        __syncthreads();
    }

    // attention weights for this thread's 8 columns
    float asw[8], adw[8];
    #pragma unroll
    for (int j = 0; j < 8; j++) {
        asw[j] = att_s[tx * 8 + j];
        adw[j] = att_d[tx * 8 + j];
    }

    #pragma unroll
    for (int i = 0; i < 8; i++) {
        int gm = m0 + ty * 8 + i;
        float ps = 0.f, pd = 0.f;
        #pragma unroll
        for (int j = 0; j < 8; j++) {
            ps += acc[i][j] * asw[j];
            pd += acc[i][j] * adw[j];
        }
        // reduce over the 16 tx-threads (lane = (ty&1)*16 + tx)
        #pragma unroll
        for (int o = 8; o; o >>= 1) {
            ps += __shfl_down_sync(0xffffffffu, ps, o, 16);
            pd += __shfl_down_sync(0xffffffffu, pd, o, 16);
        }
        if (gm < M) {
            // pack 8 fp32 -> 4 half2 -> one 16B store
            __half2 hp[4];
            #pragma unroll
            for (int j = 0; j < 4; j++)
                hp[j] = __floats2half2_rn(acc[i][2 * j], acc[i][2 * j + 1]);
            *(int4*)(g_h16 + (size_t)gm * H + tx * 8) = *(const int4*)hp;
            if (tx == 0) { g_as[gm] = ps; g_ad[gm] = pd; }
        }
    }
}

// ---------------- aggregation: warp per dst node, fp16 gather, unroll 4 ------
// out[n][:] = relu( (Σ_e w_e h[src_e]) / (Σ_e w_e) + bias ),
// w_e = exp(leaky_relu(a_s[src] + a_d[n]))   (exp(e)/Σexp(e) == softmax)
__device__ __forceinline__ float lrexp(float e) {
    e = e > 0.f ? e : NEG_SLOPE * e;
    return __expf(e);
}

// load 4 halves (8B) at row a, cols lane*4..lane*4+3, as float4
__device__ __forceinline__ float4 h16_load(int a, int lane) {
    uint2 v = *(const uint2*)(g_h16 + (size_t)a * H + lane * 4);
    float2 f0 = __half22float2(*(const __half2*)&v.x);
    float2 f1 = __half22float2(*(const __half2*)&v.y);
    return make_float4(f0.x, f0.y, f1.x, f1.y);
}

template<bool TAIL>
__global__ void k_agg(const float* __restrict__ bias,
                      const float* __restrict__ Wr, const float* __restrict__ br,
                      const float* __restrict__ Wc, const float* __restrict__ bc,
                      float* __restrict__ out) {
    int warp = threadIdx.x >> 5;
    int lane = threadIdx.x & 31;
    int n = blockIdx.x * 4 + warp;
    __shared__ float s0s[4], s1s[4];

    int s = g_off[n], e = g_off[n + 1];
    float ad = g_ad[n];
    float4 acc = make_float4(0.f, 0.f, 0.f, 0.f);
    float z = 0.f;

    int p = s;
    for (; p + 4 <= e; p += 4) {
        int a0 = __ldg(&g_psrc[p]);
        int a1 = __ldg(&g_psrc[p + 1]);
        int a2 = __ldg(&g_psrc[p + 2]);
        int a3 = __ldg(&g_psrc[p + 3]);
        float w0 = lrexp(g_as[a0] + ad);
        float w1 = lrexp(g_as[a1] + ad);
        float w2 = lrexp(g_as[a2] + ad);
        float w3 = lrexp(g_as[a3] + ad);
        float4 h0 = h16_load(a0, lane);
        float4 h1 = h16_load(a1, lane);
        float4 h2 = h16_load(a2, lane);
        float4 h3 = h16_load(a3, lane);
        z += (w0 + w1) + (w2 + w3);
        acc.x += w0 * h0.x + w1 * h1.x + w2 * h2.x + w3 * h3.x;
        acc.y += w0 * h0.y + w1 * h1.y + w2 * h2.y + w3 * h3.y;
        acc.z += w0 * h0.z + w1 * h1.z + w2 * h2.z + w3 * h3.z;
        acc.w += w0 * h0.w + w1 * h1.w + w2 * h2.w + w3 * h3.w;
    }
    for (; p < e; p++) {
        int a0 = __ldg(&g_psrc[p]);
        float w0 = lrexp(g_as[a0] + ad);
        float4 h0 = h16_load(a0, lane);
        z += w0;
        acc.x += w0 * h0.x; acc.y += w0 * h0.y;
        acc.z += w0 * h0.z; acc.w += w0 * h0.w;
    }

    float inv = 1.0f / z;
    float4 b4 = ((const float4*)bias)[lane];
    float4 v;
    v.x = fmaxf(acc.x * inv + b4.x, 0.f);
    v.y = fmaxf(acc.y * inv + b4.y, 0.f);
    v.z = fmaxf(acc.z * inv + b4.z, 0.f);
    v.w = fmaxf(acc.w * inv + b4.w, 0.f);

    if (!TAIL) {
        ((float4*)g_hn)[(size_t)n * 32 + lane] = v;
    } else {
        // fused tail: r = v·Wr + br ; acc2 += r * Wc[n]; last block writes out
        float4 wr = ((const float4*)Wr)[lane];
        float dot = v.x * wr.x + v.y * wr.y + v.z * wr.z + v.w * wr.w;
        #pragma unroll
        for (int o = 16; o; o >>= 1) dot += __shfl_down_sync(0xffffffffu, dot, o);
        if (lane == 0) {
            float r = dot + br[0];
            s0s[warp] = r * Wc[n * 2 + 0];
            s1s[warp] = r * Wc[n * 2 + 1];
        }
        __syncthreads();
        if (threadIdx.x == 0) {
            atomicAdd(&g_acc2[0], s0s[0] + s0s[1] + s0s[2] + s0s[3]);
            atomicAdd(&g_acc2[1], s1s[0] + s1s[1] + s1s[2] + s1s[3]);
            __threadfence();
            int old = atomicAdd(&g_done, 1);
            if (old == gridDim.x - 1) {
                g_done = 0;  // reset for next graph replay
                float r0 = atomicAdd(&g_acc2[0], 0.0f);
                float r1 = atomicAdd(&g_acc2[1], 0.0f);
                out[0] = r0 + bc[0];
                out[1] = r1 + bc[1];
            }
        }
    }
}

// ---------------- launch -------------------------------------------------------
extern "C" void kernel_launch(void* const* d_in, const int* in_sizes, int n_in,
                              void* d_out, int out_size) {
    const float* x   = (const float*)d_in[0];
    const int*   ei  = (const int*)  d_in[1];
    const float* W1  = (const float*)d_in[2];
    const float* as1 = (const float*)d_in[3];
    const float* ad1 = (const float*)d_in[4];
    const float* b1  = (const float*)d_in[5];
    const float* W2  = (const float*)d_in[6];
    const float* as2 = (const float*)d_in[7];
    const float* ad2 = (const float*)d_in[8];
    const float* b2  = (const float*)d_in[9];
    const float* Wr  = (const float*)d_in[10];
    const float* br  = (const float*)d_in[11];
    const float* Wc  = (const float*)d_in[12];
    const float* bc  = (const float*)d_in[13];
    float* out = (float*)d_out;

    // CSR build
    k_init <<<(N_NODES + 255) / 256, 256>>>();
    k_hist <<<(ETOT / 4 + 255) / 256, 256>>>(ei);
    k_scan <<<1, 1024>>>();
    k_place<<<(ETOT / 4 + 255) / 256, 256>>>(ei);

    int gemm_grid = (N_NODES + BM - 1) / BM;

    // layer 1
    k_gemm<<<gemm_grid, 128>>>(x, W1, as1, ad1, N_NODES, F_IN);
    k_agg<false><<<N_NODES / 4, 128>>>(b1, nullptr, nullptr, nullptr, nullptr, nullptr);

    // layer 2 (+ fused tail and final output)
    k_gemm<<<gemm_grid, 128>>>(nullptr, W2, as2, ad2, N_NODES, H);
    k_agg<true><<<N_NODES / 4, 128>>>(b2, Wr, br, Wc, bc, out);
}

// round 6
// speedup vs baseline: 1.4857x; 1.3650x over previous
#include <cuda_runtime.h>
#include <cuda_fp16.h>
#include <mma.h>

using namespace nvcuda;

#define N_NODES 10000
#define N_EDGES 320000
#define ETOT    330000
#define H       128
#define F_IN    256
#define NEG_SLOPE 0.2f

// ---------------- scratch ----------------------------------------------------
__device__ __half g_h16 [N_NODES * H];  // GEMM output, fp16 (gather source)
__device__ __half g_hn16[N_NODES * H];  // post-GAT relu output, fp16 (GEMM2 A)
__device__ float  g_as [N_NODES];
__device__ float  g_ad [N_NODES];
__device__ int    g_cnt[N_NODES];
__device__ int    g_off[N_NODES + 1];
__device__ int    g_rank[ETOT];
__device__ int    g_psrc[ETOT];
__device__ float  g_acc2[2];
__device__ int    g_done;

// ---------------- init -------------------------------------------------------
__global__ void k_init() {
    int i = blockIdx.x * blockDim.x + threadIdx.x;
    if (i < N_NODES) g_cnt[i] = 0;
    if (i < 2) g_acc2[i] = 0.0f;
}

// ---------------- histogram + per-edge rank, 4 edges/thread ------------------
__global__ void k_hist(const int* __restrict__ ei) {
    int i = (blockIdx.x * blockDim.x + threadIdx.x) * 4;
    if (i >= ETOT) return;
    if (i < N_EDGES) {
        int4 d4 = *(const int4*)(ei + N_EDGES + i);
        int4 r4;
        r4.x = atomicAdd(&g_cnt[d4.x], 1);
        r4.y = atomicAdd(&g_cnt[d4.y], 1);
        r4.z = atomicAdd(&g_cnt[d4.z], 1);
        r4.w = atomicAdd(&g_cnt[d4.w], 1);
        *(int4*)(g_rank + i) = r4;
    } else {
        int4 r4;
        int d = i - N_EDGES;
        r4.x = atomicAdd(&g_cnt[d + 0], 1);
        r4.y = atomicAdd(&g_cnt[d + 1], 1);
        r4.z = atomicAdd(&g_cnt[d + 2], 1);
        r4.w = atomicAdd(&g_cnt[d + 3], 1);
        *(int4*)(g_rank + i) = r4;
    }
}

__global__ void k_scan() {   // single block, 1024 threads
    __shared__ int sd[1024];
    const int CH = (N_NODES + 1023) / 1024;   // 10
    int t = threadIdx.x;
    int base = t * CH;
    int local[CH];
    int sum = 0;
    #pragma unroll
    for (int k = 0; k < CH; k++) {
        int i = base + k;
        int c = (i < N_NODES) ? g_cnt[i] : 0;
        local[k] = sum;
        sum += c;
    }
    sd[t] = sum;
    __syncthreads();
    for (int o = 1; o < 1024; o <<= 1) {
        int v = (t >= o) ? sd[t - o] : 0;
        __syncthreads();
        sd[t] += v;
        __syncthreads();
    }
    int excl = sd[t] - sum;
    #pragma unroll
    for (int k = 0; k < CH; k++) {
        int i = base + k;
        if (i < N_NODES) g_off[i] = excl + local[k];
    }
    if (t == 0) g_off[N_NODES] = ETOT;
}

__global__ void k_place(const int* __restrict__ ei) {
    int i = (blockIdx.x * blockDim.x + threadIdx.x) * 4;
    if (i >= ETOT) return;
    int4 r4 = *(const int4*)(g_rank + i);
    if (i < N_EDGES) {
        int4 s4 = *(const int4*)(ei + i);
        int4 d4 = *(const int4*)(ei + N_EDGES + i);
        int o0 = g_off[d4.x], o1 = g_off[d4.y], o2 = g_off[d4.z], o3 = g_off[d4.w];
        g_psrc[o0 + r4.x] = s4.x;
        g_psrc[o1 + r4.y] = s4.y;
        g_psrc[o2 + r4.z] = s4.z;
        g_psrc[o3 + r4.w] = s4.w;
    } else {
        int d = i - N_EDGES;
        int o0 = g_off[d + 0], o1 = g_off[d + 1], o2 = g_off[d + 2], o3 = g_off[d + 3];
        g_psrc[o0 + r4.x] = d + 0;
        g_psrc[o1 + r4.y] = d + 1;
        g_psrc[o2 + r4.z] = d + 2;
        g_psrc[o3 + r4.w] = d + 3;
    }
}

// ---------------- wmma GEMM + fused attention dots ---------------------------
// h[M,128] = A[M,K] @ B[K,128] in fp16 (fp32 accumulate); h stored fp16.
// Also g_as[m]=h[m]·att_s, g_ad[m]=h[m]·att_d (fp32, from fp32 accumulators).
// BM=64, BN=128, BK=32, 128 threads = 4 warps; warp w owns rows w*16..w*16+15.
#define BM 64
#define BN 128
#define BK 32
#define LDA 40     // A smem leading dim (fp16), mult of 8
#define LDB 136    // B smem leading dim (fp16), mult of 8
#define LDC 136    // C smem leading dim (fp32), mult of 4

__global__ __launch_bounds__(128, 2)
void k_gemm(const float* __restrict__ A32, const float* __restrict__ B,
            const float* __restrict__ att_s, const float* __restrict__ att_d,
            int M, int K) {
    // shared: phase 1 = As (fp16 64xLDA) + Bs (fp16 32xLDB); phase 2 = Cs (fp32 64xLDC)
    __shared__ char smem_raw[BM * LDC * 4];   // 34816 B
    __half* As  = (__half*)smem_raw;                       // [BM][LDA]
    __half* Bs  = (__half*)(smem_raw + BM * LDA * 2);      // [BK][LDB]
    float*  Cs  = (float*)smem_raw;                        // [BM][LDC]

    int tid  = threadIdx.x;
    int warp = tid >> 5;
    int m0   = blockIdx.x * BM;

    wmma::fragment<wmma::accumulator, 16, 16, 16, float> c[8];
    #pragma unroll
    for (int n = 0; n < 8; n++) wmma::fill_fragment(c[n], 0.0f);

    for (int k0 = 0; k0 < K; k0 += BK) {
        // --- load A tile 64x32 -> fp16 smem. thread: row=tid>>1, 16-col seg=(tid&1)*16
        {
            int r  = tid >> 1;
            int cg = (tid & 1) * 16;
            int gm = m0 + r;
            __half hv[16];
            if (gm < M) {
                if (A32) {
                    const float* src = A32 + (size_t)gm * K + k0 + cg;
                    #pragma unroll
                    for (int q = 0; q < 4; q++) {
                        float4 f = *(const float4*)(src + q * 4);
                        hv[q * 4 + 0] = __float2half_rn(f.x);
                        hv[q * 4 + 1] = __float2half_rn(f.y);
                        hv[q * 4 + 2] = __float2half_rn(f.z);
                        hv[q * 4 + 3] = __float2half_rn(f.w);
                    }
                } else {
                    const __half* src = g_hn16 + (size_t)gm * K + k0 + cg;
                    *(uint4*)hv = *(const uint4*)src;
                    *(uint4*)(hv + 8) = *(const uint4*)(src + 8);
                }
            } else {
                #pragma unroll
                for (int q = 0; q < 16; q++) hv[q] = __float2half_rn(0.f);
            }
            __half* dst = As + r * LDA + cg;
            *(uint4*)dst = *(const uint4*)hv;
            *(uint4*)(dst + 8) = *(const uint4*)(hv + 8);
        }
        // --- load B tile 32x128 -> fp16 smem. thread: row=tid>>2, 32-col seg=(tid&3)*32
        {
            int r  = tid >> 2;
            int cg = (tid & 3) * 32;
            const float* src = B + (size_t)(k0 + r) * BN + cg;
            __half hv[32];
            #pragma unroll
            for (int q = 0; q < 8; q++) {
                float4 f = *(const float4*)(src + q * 4);
                hv[q * 4 + 0] = __float2half_rn(f.x);
                hv[q * 4 + 1] = __float2half_rn(f.y);
                hv[q * 4 + 2] = __float2half_rn(f.z);
                hv[q * 4 + 3] = __float2half_rn(f.w);
            }
            __half* dst = Bs + r * LDB + cg;
            #pragma unroll
            for (int q = 0; q < 4; q++)
                *(uint4*)(dst + q * 8) = *(const uint4*)(hv + q * 8);
        }
        __syncthreads();

        // --- MMA: warp strip 16 rows x 128 cols, two k-subtiles
        #pragma unroll
        for (int ks = 0; ks < BK; ks += 16) {
            wmma::fragment<wmma::matrix_a, 16, 16, 16, __half, wmma::row_major> a;
            wmma::load_matrix_sync(a, As + (warp * 16) * LDA + ks, LDA);
            #pragma unroll
            for (int n = 0; n < 8; n++) {
                wmma::fragment<wmma::matrix_b, 16, 16, 16, __half, wmma::row_major> bfr;
                wmma::load_matrix_sync(bfr, Bs + ks * LDB + n * 16, LDB);
                wmma::mma_sync(c[n], a, bfr, c[n]);
            }
        }
        __syncthreads();
    }

    // --- epilogue: dump accumulators to smem (fp32), then fuse att dots + fp16 store
    #pragma unroll
    for (int n = 0; n < 8; n++)
        wmma::store_matrix_sync(Cs + (warp * 16) * LDC + n * 16, c[n], LDC,
                                wmma::mem_row_major);
    __syncthreads();

    {
        int r    = tid >> 1;          // 0..63
        int half = tid & 1;           // 0..1 -> cols half*64..
        int gm   = m0 + r;
        const float* crow = Cs + r * LDC + half * 64;
        float ps = 0.f, pd = 0.f;
        __half hv[64];
        #pragma unroll
        for (int q = 0; q < 64; q += 4) {
            float4 f = *(const float4*)(crow + q);
            int col = half * 64 + q;
            ps += f.x * att_s[col]     + f.y * att_s[col + 1]
                + f.z * att_s[col + 2] + f.w * att_s[col + 3];
            pd += f.x * att_d[col]     + f.y * att_d[col + 1]
                + f.z * att_d[col + 2] + f.w * att_d[col + 3];
            hv[q + 0] = __float2half_rn(f.x);
            hv[q + 1] = __float2half_rn(f.y);
            hv[q + 2] = __float2half_rn(f.z);
            hv[q + 3] = __float2half_rn(f.w);
        }
        // pair-reduce (threads t, t^1 share row r)
        ps += __shfl_xor_sync(0xffffffffu, ps, 1);
        pd += __shfl_xor_sync(0xffffffffu, pd, 1);
        if (gm < M) {
            __half* dst = g_h16 + (size_t)gm * H + half * 64;
            #pragma unroll
            for (int q = 0; q < 8; q++)
                *(uint4*)(dst + q * 8) = *(const uint4*)(hv + q * 8);
            if (half == 0) { g_as[gm] = ps; g_ad[gm] = pd; }
        }
    }
}

// ---------------- aggregation: warp per dst node, fp16 gather, unroll 4 ------
__device__ __forceinline__ float lrexp(float e) {
    e = e > 0.f ? e : NEG_SLOPE * e;
    return __expf(e);
}

__device__ __forceinline__ float4 h16_load(int a, int lane) {
    uint2 v = *(const uint2*)(g_h16 + (size_t)a * H + lane * 4);
    float2 f0 = __half22float2(*(const __half2*)&v.x);
    float2 f1 = __half22float2(*(const __half2*)&v.y);
    return make_float4(f0.x, f0.y, f1.x, f1.y);
}

template<bool TAIL>
__global__ void k_agg(const float* __restrict__ bias,
                      const float* __restrict__ Wr, const float* __restrict__ br,
                      const float* __restrict__ Wc, const float* __restrict__ bc,
                      float* __restrict__ out) {
    int warp = threadIdx.x >> 5;
    int lane = threadIdx.x & 31;
    int n = blockIdx.x * 4 + warp;
    __shared__ float s0s[4], s1s[4];

    int s = g_off[n], e = g_off[n + 1];
    float ad = g_ad[n];
    float4 acc = make_float4(0.f, 0.f, 0.f, 0.f);
    float z = 0.f;

    int p = s;
    for (; p + 4 <= e; p += 4) {
        int a0 = __ldg(&g_psrc[p]);
        int a1 = __ldg(&g_psrc[p + 1]);
        int a2 = __ldg(&g_psrc[p + 2]);
        int a3 = __ldg(&g_psrc[p + 3]);
        float w0 = lrexp(g_as[a0] + ad);
        float w1 = lrexp(g_as[a1] + ad);
        float w2 = lrexp(g_as[a2] + ad);
        float w3 = lrexp(g_as[a3] + ad);
        float4 h0 = h16_load(a0, lane);
        float4 h1 = h16_load(a1, lane);
        float4 h2 = h16_load(a2, lane);
        float4 h3 = h16_load(a3, lane);
        z += (w0 + w1) + (w2 + w3);
        acc.x += w0 * h0.x + w1 * h1.x + w2 * h2.x + w3 * h3.x;
        acc.y += w0 * h0.y + w1 * h1.y + w2 * h2.y + w3 * h3.y;
        acc.z += w0 * h0.z + w1 * h1.z + w2 * h2.z + w3 * h3.z;
        acc.w += w0 * h0.w + w1 * h1.w + w2 * h2.w + w3 * h3.w;
    }
    for (; p < e; p++) {
        int a0 = __ldg(&g_psrc[p]);
        float w0 = lrexp(g_as[a0] + ad);
        float4 h0 = h16_load(a0, lane);
        z += w0;
        acc.x += w0 * h0.x; acc.y += w0 * h0.y;
        acc.z += w0 * h0.z; acc.w += w0 * h0.w;
    }

    float inv = 1.0f / z;
    float4 b4 = ((const float4*)bias)[lane];
    float4 v;
    v.x = fmaxf(acc.x * inv + b4.x, 0.f);
    v.y = fmaxf(acc.y * inv + b4.y, 0.f);
    v.z = fmaxf(acc.z * inv + b4.z, 0.f);
    v.w = fmaxf(acc.w * inv + b4.w, 0.f);

    if (!TAIL) {
        __half2 hp[2];
        hp[0] = __floats2half2_rn(v.x, v.y);
        hp[1] = __floats2half2_rn(v.z, v.w);
        *(uint2*)(g_hn16 + (size_t)n * H + lane * 4) = *(const uint2*)hp;
    } else {
        float4 wr = ((const float4*)Wr)[lane];
        float dot = v.x * wr.x + v.y * wr.y + v.z * wr.z + v.w * wr.w;
        #pragma unroll
        for (int o = 16; o; o >>= 1) dot += __shfl_down_sync(0xffffffffu, dot, o);
        if (lane == 0) {
            float r = dot + br[0];
            s0s[warp] = r * Wc[n * 2 + 0];
            s1s[warp] = r * Wc[n * 2 + 1];
        }
        __syncthreads();
        if (threadIdx.x == 0) {
            atomicAdd(&g_acc2[0], s0s[0] + s0s[1] + s0s[2] + s0s[3]);
            atomicAdd(&g_acc2[1], s1s[0] + s1s[1] + s1s[2] + s1s[3]);
            __threadfence();
            int old = atomicAdd(&g_done, 1);
            if (old == gridDim.x - 1) {
                g_done = 0;  // reset for next graph replay
                float r0 = atomicAdd(&g_acc2[0], 0.0f);
                float r1 = atomicAdd(&g_acc2[1], 0.0f);
                out[0] = r0 + bc[0];
                out[1] = r1 + bc[1];
            }
        }
    }
}

// ---------------- launch -------------------------------------------------------
extern "C" void kernel_launch(void* const* d_in, const int* in_sizes, int n_in,
                              void* d_out, int out_size) {
    const float* x   = (const float*)d_in[0];
    const int*   ei  = (const int*)  d_in[1];
    const float* W1  = (const float*)d_in[2];
    const float* as1 = (const float*)d_in[3];
    const float* ad1 = (const float*)d_in[4];
    const float* b1  = (const float*)d_in[5];
    const float* W2  = (const float*)d_in[6];
    const float* as2 = (const float*)d_in[7];
    const float* ad2 = (const float*)d_in[8];
    const float* b2  = (const float*)d_in[9];
    const float* Wr  = (const float*)d_in[10];
    const float* br  = (const float*)d_in[11];
    const float* Wc  = (const float*)d_in[12];
    const float* bc  = (const float*)d_in[13];
    float* out = (float*)d_out;

    // CSR build
    k_init <<<(N_NODES + 255) / 256, 256>>>();
    k_hist <<<(ETOT / 4 + 255) / 256, 256>>>(ei);
    k_scan <<<1, 1024>>>();
    k_place<<<(ETOT / 4 + 255) / 256, 256>>>(ei);

    int gemm_grid = (N_NODES + BM - 1) / BM;

    // layer 1
    k_gemm<<<gemm_grid, 128>>>(x, W1, as1, ad1, N_NODES, F_IN);
    k_agg<false><<<N_NODES / 4, 128>>>(b1, nullptr, nullptr, nullptr, nullptr, nullptr);

    // layer 2 (+ fused tail and final output)
    k_gemm<<<gemm_grid, 128>>>(nullptr, W2, as2, ad2, N_NODES, H);
    k_agg<true><<<N_NODES / 4, 128>>>(b2, Wr, br, Wc, bc, out);
}

// round 7
// speedup vs baseline: 1.7464x; 1.1754x over previous
#include <cuda_runtime.h>
#include <cuda_fp16.h>
#include <mma.h>

using namespace nvcuda;

#define N_NODES 10000
#define N_EDGES 320000
#define ETOT    330000
#define H       128
#define F_IN    256
#define NEG_SLOPE 0.2f

// ---------------- scratch ----------------------------------------------------
__device__ __half g_h16 [N_NODES * H];  // GEMM output, fp16 (gather source)
__device__ __half g_hn16[N_NODES * H];  // post-GAT relu output, fp16 (GEMM2 A)
__device__ float  g_as [N_NODES];
__device__ float  g_ad [N_NODES];
__device__ int    g_cnt[N_NODES];       // invariant: zero at entry of every call
__device__ int    g_off[N_NODES + 1];
__device__ int    g_rank[ETOT];
__device__ int    g_psrc[ETOT];
__device__ float  g_acc2[2];            // invariant: zero at entry of every call
__device__ int    g_done;               // invariant: zero at entry of every call

// ---------------- histogram + per-edge rank, 4 edges/thread ------------------
__global__ void k_hist(const int* __restrict__ ei) {
    int i = (blockIdx.x * blockDim.x + threadIdx.x) * 4;
    if (i >= ETOT) return;
    if (i < N_EDGES) {
        int4 d4 = *(const int4*)(ei + N_EDGES + i);
        int4 r4;
        r4.x = atomicAdd(&g_cnt[d4.x], 1);
        r4.y = atomicAdd(&g_cnt[d4.y], 1);
        r4.z = atomicAdd(&g_cnt[d4.z], 1);
        r4.w = atomicAdd(&g_cnt[d4.w], 1);
        *(int4*)(g_rank + i) = r4;
    } else {
        int4 r4;
        int d = i - N_EDGES;
        r4.x = atomicAdd(&g_cnt[d + 0], 1);
        r4.y = atomicAdd(&g_cnt[d + 1], 1);
        r4.z = atomicAdd(&g_cnt[d + 2], 1);
        r4.w = atomicAdd(&g_cnt[d + 3], 1);
        *(int4*)(g_rank + i) = r4;
    }
}

// ---------------- scan (warp-shuffle, 1 block x 1024) + g_cnt self-reset -----
__global__ void k_scan() {
    const int CH = 10;
    int t = threadIdx.x;
    int lane = t & 31, wid = t >> 5;
    int base = t * CH;
    int local[CH];
    int sum = 0;
    #pragma unroll
    for (int k = 0; k < CH; k++) {
        int i = base + k;
        int c = (i < N_NODES) ? g_cnt[i] : 0;
        local[k] = sum;
        sum += c;
    }
    int tot = sum;
    int incl = tot;
    #pragma unroll
    for (int o = 1; o < 32; o <<= 1) {
        int v = __shfl_up_sync(0xffffffffu, incl, o);
        if (lane >= o) incl += v;
    }
    __shared__ int wsum[32];
    if (lane == 31) wsum[wid] = incl;
    __syncthreads();
    if (wid == 0) {
        int v = wsum[lane];
        #pragma unroll
        for (int o = 1; o < 32; o <<= 1) {
            int u = __shfl_up_sync(0xffffffffu, v, o);
            if (lane >= o) v += u;
        }
        wsum[lane] = v;
    }
    __syncthreads();
    int excl = incl - tot + (wid > 0 ? wsum[wid - 1] : 0);
    #pragma unroll
    for (int k = 0; k < CH; k++) {
        int i = base + k;
        if (i < N_NODES) {
            g_off[i] = excl + local[k];
            g_cnt[i] = 0;              // restore invariant for next call
        }
    }
    if (t == 0) g_off[N_NODES] = ETOT;
}

__global__ void k_place(const int* __restrict__ ei) {
    int i = (blockIdx.x * blockDim.x + threadIdx.x) * 4;
    if (i >= ETOT) return;
    int4 r4 = *(const int4*)(g_rank + i);
    if (i < N_EDGES) {
        int4 s4 = *(const int4*)(ei + i);
        int4 d4 = *(const int4*)(ei + N_EDGES + i);
        int o0 = g_off[d4.x], o1 = g_off[d4.y], o2 = g_off[d4.z], o3 = g_off[d4.w];
        g_psrc[o0 + r4.x] = s4.x;
        g_psrc[o1 + r4.y] = s4.y;
        g_psrc[o2 + r4.z] = s4.z;
        g_psrc[o3 + r4.w] = s4.w;
    } else {
        int d = i - N_EDGES;
        int o0 = g_off[d + 0], o1 = g_off[d + 1], o2 = g_off[d + 2], o3 = g_off[d + 3];
        g_psrc[o0 + r4.x] = d + 0;
        g_psrc[o1 + r4.y] = d + 1;
        g_psrc[o2 + r4.z] = d + 2;
        g_psrc[o3 + r4.w] = d + 3;
    }
}

// ---------------- wmma GEMM + fused attention dots ---------------------------
#define BM 64
#define BN 128
#define BK 32
#define LDA 40
#define LDB 136
#define LDC 136

__global__ __launch_bounds__(128, 2)
void k_gemm(const float* __restrict__ A32, const float* __restrict__ B,
            const float* __restrict__ att_s, const float* __restrict__ att_d,
            int M, int K) {
    __shared__ char smem_raw[BM * LDC * 4];
    __half* As  = (__half*)smem_raw;                       // [BM][LDA]
    __half* Bs  = (__half*)(smem_raw + BM * LDA * 2);      // [BK][LDB]
    float*  Cs  = (float*)smem_raw;                        // [BM][LDC]

    int tid  = threadIdx.x;
    int warp = tid >> 5;
    int m0   = blockIdx.x * BM;

    wmma::fragment<wmma::accumulator, 16, 16, 16, float> c[8];
    #pragma unroll
    for (int n = 0; n < 8; n++) wmma::fill_fragment(c[n], 0.0f);

    for (int k0 = 0; k0 < K; k0 += BK) {
        {   // A tile 64x32 -> fp16 smem
            int r  = tid >> 1;
            int cg = (tid & 1) * 16;
            int gm = m0 + r;
            __half hv[16];
            if (gm < M) {
                if (A32) {
                    const float* src = A32 + (size_t)gm * K + k0 + cg;
                    #pragma unroll
                    for (int q = 0; q < 4; q++) {
                        float4 f = *(const float4*)(src + q * 4);
                        hv[q * 4 + 0] = __float2half_rn(f.x);
                        hv[q * 4 + 1] = __float2half_rn(f.y);
                        hv[q * 4 + 2] = __float2half_rn(f.z);
                        hv[q * 4 + 3] = __float2half_rn(f.w);
                    }
                } else {
                    const __half* src = g_hn16 + (size_t)gm * K + k0 + cg;
                    *(uint4*)hv = *(const uint4*)src;
                    *(uint4*)(hv + 8) = *(const uint4*)(src + 8);
                }
            } else {
                #pragma unroll
                for (int q = 0; q < 16; q++) hv[q] = __float2half_rn(0.f);
            }
            __half* dst = As + r * LDA + cg;
            *(uint4*)dst = *(const uint4*)hv;
            *(uint4*)(dst + 8) = *(const uint4*)(hv + 8);
        }
        {   // B tile 32x128 -> fp16 smem
            int r  = tid >> 2;
            int cg = (tid & 3) * 32;
            const float* src = B + (size_t)(k0 + r) * BN + cg;
            __half hv[32];
            #pragma unroll
            for (int q = 0; q < 8; q++) {
                float4 f = *(const float4*)(src + q * 4);
                hv[q * 4 + 0] = __float2half_rn(f.x);
                hv[q * 4 + 1] = __float2half_rn(f.y);
                hv[q * 4 + 2] = __float2half_rn(f.z);
                hv[q * 4 + 3] = __float2half_rn(f.w);
            }
            __half* dst = Bs + r * LDB + cg;
            #pragma unroll
            for (int q = 0; q < 4; q++)
                *(uint4*)(dst + q * 8) = *(const uint4*)(hv + q * 8);
        }
        __syncthreads();

        #pragma unroll
        for (int ks = 0; ks < BK; ks += 16) {
            wmma::fragment<wmma::matrix_a, 16, 16, 16, __half, wmma::row_major> a;
            wmma::load_matrix_sync(a, As + (warp * 16) * LDA + ks, LDA);
            #pragma unroll
            for (int n = 0; n < 8; n++) {
                wmma::fragment<wmma::matrix_b, 16, 16, 16, __half, wmma::row_major> bfr;
                wmma::load_matrix_sync(bfr, Bs + ks * LDB + n * 16, LDB);
                wmma::mma_sync(c[n], a, bfr, c[n]);
            }
        }
        __syncthreads();
    }

    #pragma unroll
    for (int n = 0; n < 8; n++)
        wmma::store_matrix_sync(Cs + (warp * 16) * LDC + n * 16, c[n], LDC,
                                wmma::mem_row_major);
    __syncthreads();

    {
        int r    = tid >> 1;
        int half = tid & 1;
        int gm   = m0 + r;
        const float* crow = Cs + r * LDC + half * 64;
        float ps = 0.f, pd = 0.f;
        __half hv[64];
        #pragma unroll
        for (int q = 0; q < 64; q += 4) {
            float4 f = *(const float4*)(crow + q);
            int col = half * 64 + q;
            ps += f.x * att_s[col]     + f.y * att_s[col + 1]
                + f.z * att_s[col + 2] + f.w * att_s[col + 3];
            pd += f.x * att_d[col]     + f.y * att_d[col + 1]
                + f.z * att_d[col + 2] + f.w * att_d[col + 3];
            hv[q + 0] = __float2half_rn(f.x);
            hv[q + 1] = __float2half_rn(f.y);
            hv[q + 2] = __float2half_rn(f.z);
            hv[q + 3] = __float2half_rn(f.w);
        }
        ps += __shfl_xor_sync(0xffffffffu, ps, 1);
        pd += __shfl_xor_sync(0xffffffffu, pd, 1);
        if (gm < M) {
            __half* dst = g_h16 + (size_t)gm * H + half * 64;
            #pragma unroll
            for (int q = 0; q < 8; q++)
                *(uint4*)(dst + q * 8) = *(const uint4*)(hv + q * 8);
            if (half == 0) { g_as[gm] = ps; g_ad[gm] = pd; }
        }
    }
}

// ---------------- aggregation: warp per dst node, fp16 gather, unroll 8 ------
__device__ __forceinline__ float lrexp(float e) {
    e = e > 0.f ? e : NEG_SLOPE * e;
    return __expf(e);
}

__device__ __forceinline__ float4 h16_load(int a, int lane) {
    uint2 v = *(const uint2*)(g_h16 + (size_t)a * H + lane * 4);
    float2 f0 = __half22float2(*(const __half2*)&v.x);
    float2 f1 = __half22float2(*(const __half2*)&v.y);
    return make_float4(f0.x, f0.y, f1.x, f1.y);
}

template<bool TAIL>
__global__ void k_agg(const float* __restrict__ bias,
                      const float* __restrict__ Wr, const float* __restrict__ br,
                      const float* __restrict__ Wc, const float* __restrict__ bc,
                      float* __restrict__ out) {
    int warp = threadIdx.x >> 5;
    int lane = threadIdx.x & 31;
    int n = blockIdx.x * 4 + warp;
    __shared__ float s0s[4], s1s[4];

    int s = g_off[n], e = g_off[n + 1];
    float ad = g_ad[n];
    float4 acc = make_float4(0.f, 0.f, 0.f, 0.f);
    float z = 0.f;

    int p = s;
    for (; p + 8 <= e; p += 8) {
        int idx[8];
        #pragma unroll
        for (int q = 0; q < 8; q++) idx[q] = __ldg(&g_psrc[p + q]);
        float w[8];
        #pragma unroll
        for (int q = 0; q < 8; q++) w[q] = lrexp(g_as[idx[q]] + ad);
        float4 hv[8];
        #pragma unroll
        for (int q = 0; q < 8; q++) hv[q] = h16_load(idx[q], lane);
        #pragma unroll
        for (int q = 0; q < 8; q++) {
            z += w[q];
            acc.x += w[q] * hv[q].x;
            acc.y += w[q] * hv[q].y;
            acc.z += w[q] * hv[q].z;
            acc.w += w[q] * hv[q].w;
        }
    }
    for (; p < e; p++) {
        int a0 = __ldg(&g_psrc[p]);
        float w0 = lrexp(g_as[a0] + ad);
        float4 h0 = h16_load(a0, lane);
        z += w0;
        acc.x += w0 * h0.x; acc.y += w0 * h0.y;
        acc.z += w0 * h0.z; acc.w += w0 * h0.w;
    }

    float inv = 1.0f / z;
    float4 b4 = ((const float4*)bias)[lane];
    float4 v;
    v.x = fmaxf(acc.x * inv + b4.x, 0.f);
    v.y = fmaxf(acc.y * inv + b4.y, 0.f);
    v.z = fmaxf(acc.z * inv + b4.z, 0.f);
    v.w = fmaxf(acc.w * inv + b4.w, 0.f);

    if (!TAIL) {
        __half2 hp[2];
        hp[0] = __floats2half2_rn(v.x, v.y);
        hp[1] = __floats2half2_rn(v.z, v.w);
        *(uint2*)(g_hn16 + (size_t)n * H + lane * 4) = *(const uint2*)hp;
    } else {
        float4 wr = ((const float4*)Wr)[lane];
        float dot = v.x * wr.x + v.y * wr.y + v.z * wr.z + v.w * wr.w;
        #pragma unroll
        for (int o = 16; o; o >>= 1) dot += __shfl_down_sync(0xffffffffu, dot, o);
        if (lane == 0) {
            float r = dot + br[0];
            s0s[warp] = r * Wc[n * 2 + 0];
            s1s[warp] = r * Wc[n * 2 + 1];
        }
        __syncthreads();
        if (threadIdx.x == 0) {
            atomicAdd(&g_acc2[0], s0s[0] + s0s[1] + s0s[2] + s0s[3]);
            atomicAdd(&g_acc2[1], s1s[0] + s1s[1] + s1s[2] + s1s[3]);
            __threadfence();
            int old = atomicAdd(&g_done, 1);
            if (old == gridDim.x - 1) {
                g_done = 0;                              // restore invariants
                float r0 = atomicAdd(&g_acc2[0], 0.0f);
                float r1 = atomicAdd(&g_acc2[1], 0.0f);
                g_acc2[0] = 0.0f;
                g_acc2[1] = 0.0f;
                out[0] = r0 + bc[0];
                out[1] = r1 + bc[1];
            }
        }
    }
}

// ---------------- launch -------------------------------------------------------
extern "C" void kernel_launch(void* const* d_in, const int* in_sizes, int n_in,
                              void* d_out, int out_size) {
    const float* x   = (const float*)d_in[0];
    const int*   ei  = (const int*)  d_in[1];
    const float* W1  = (const float*)d_in[2];
    const float* as1 = (const float*)d_in[3];
    const float* ad1 = (const float*)d_in[4];
    const float* b1  = (const float*)d_in[5];
    const float* W2  = (const float*)d_in[6];
    const float* as2 = (const float*)d_in[7];
    const float* ad2 = (const float*)d_in[8];
    const float* b2  = (const float*)d_in[9];
    const float* Wr  = (const float*)d_in[10];
    const float* br  = (const float*)d_in[11];
    const float* Wc  = (const float*)d_in[12];
    const float* bc  = (const float*)d_in[13];
    float* out = (float*)d_out;

    // side stream + events for CSR ∥ GEMM1 overlap (handles created once,
    // host-side infra only; per-call captured work is identical)
    static cudaStream_t s1 = nullptr;
    static cudaEvent_t ev0 = nullptr, ev1 = nullptr;
    if (s1 == nullptr) {
        cudaStreamCreateWithFlags(&s1, cudaStreamNonBlocking);
        cudaEventCreateWithFlags(&ev0, cudaEventDisableTiming);
        cudaEventCreateWithFlags(&ev1, cudaEventDisableTiming);
    }

    // fork: CSR build on s1
    cudaEventRecord(ev0, 0);
    cudaStreamWaitEvent(s1, ev0, 0);
    k_hist <<<(ETOT / 4 + 255) / 256, 256, 0, s1>>>(ei);
    k_scan <<<1, 1024, 0, s1>>>();
    k_place<<<(ETOT / 4 + 255) / 256, 256, 0, s1>>>(ei);
    cudaEventRecord(ev1, s1);

    int gemm_grid = (N_NODES + BM - 1) / BM;

    // GEMM1 on main stream, concurrent with CSR build
    k_gemm<<<gemm_grid, 128>>>(x, W1, as1, ad1, N_NODES, F_IN);

    // join
    cudaStreamWaitEvent(0, ev1, 0);

    k_agg<false><<<N_NODES / 4, 128>>>(b1, nullptr, nullptr, nullptr, nullptr, nullptr);

    k_gemm<<<gemm_grid, 128>>>(nullptr, W2, as2, ad2, N_NODES, H);
    k_agg<true><<<N_NODES / 4, 128>>>(b2, Wr, br, Wc, bc, out);
}

// round 8
// speedup vs baseline: 1.7866x; 1.0230x over previous
#include <cuda_runtime.h>
#include <cuda_fp16.h>
#include <mma.h>

using namespace nvcuda;

#define N_NODES 10000
#define N_EDGES 320000
#define ETOT    330000
#define H       128
#define F_IN    256
#define NEG_SLOPE 0.2f

// ---------------- scratch ----------------------------------------------------
__device__ __half g_h16 [N_NODES * H];  // GEMM output, fp16 (gather source)
__device__ __half g_hn16[N_NODES * H];  // post-GAT relu output, fp16 (GEMM2 A)
__device__ float  g_as [N_NODES];
__device__ float  g_ad [N_NODES];
__device__ int    g_cnt[N_NODES];       // invariant: zero at entry of every call
__device__ int    g_off[N_NODES + 1];
__device__ int    g_rank[ETOT];
__device__ int    g_psrc[ETOT];
__device__ float  g_acc2[2];            // invariant: zero at entry of every call
__device__ int    g_done;               // invariant: zero at entry of every call

// ---------------- histogram + per-edge rank, 4 edges/thread ------------------
__global__ void k_hist(const int* __restrict__ ei) {
    int i = (blockIdx.x * blockDim.x + threadIdx.x) * 4;
    if (i >= ETOT) return;
    if (i < N_EDGES) {
        int4 d4 = *(const int4*)(ei + N_EDGES + i);
        int4 r4;
        r4.x = atomicAdd(&g_cnt[d4.x], 1);
        r4.y = atomicAdd(&g_cnt[d4.y], 1);
        r4.z = atomicAdd(&g_cnt[d4.z], 1);
        r4.w = atomicAdd(&g_cnt[d4.w], 1);
        *(int4*)(g_rank + i) = r4;
    } else {
        int4 r4;
        int d = i - N_EDGES;
        r4.x = atomicAdd(&g_cnt[d + 0], 1);
        r4.y = atomicAdd(&g_cnt[d + 1], 1);
        r4.z = atomicAdd(&g_cnt[d + 2], 1);
        r4.w = atomicAdd(&g_cnt[d + 3], 1);
        *(int4*)(g_rank + i) = r4;
    }
}

// ---------------- scan (warp-shuffle, 1 block x 1024) + g_cnt self-reset -----
__global__ void k_scan() {
    const int CH = 10;
    int t = threadIdx.x;
    int lane = t & 31, wid = t >> 5;
    int base = t * CH;
    int local[CH];
    int sum = 0;
    #pragma unroll
    for (int k = 0; k < CH; k++) {
        int i = base + k;
        int c = (i < N_NODES) ? g_cnt[i] : 0;
        local[k] = sum;
        sum += c;
    }
    int tot = sum;
    int incl = tot;
    #pragma unroll
    for (int o = 1; o < 32; o <<= 1) {
        int v = __shfl_up_sync(0xffffffffu, incl, o);
        if (lane >= o) incl += v;
    }
    __shared__ int wsum[32];
    if (lane == 31) wsum[wid] = incl;
    __syncthreads();
    if (wid == 0) {
        int v = wsum[lane];
        #pragma unroll
        for (int o = 1; o < 32; o <<= 1) {
            int u = __shfl_up_sync(0xffffffffu, v, o);
            if (lane >= o) v += u;
        }
        wsum[lane] = v;
    }
    __syncthreads();
    int excl = incl - tot + (wid > 0 ? wsum[wid - 1] : 0);
    #pragma unroll
    for (int k = 0; k < CH; k++) {
        int i = base + k;
        if (i < N_NODES) {
            g_off[i] = excl + local[k];
            g_cnt[i] = 0;              // restore invariant for next call
        }
    }
    if (t == 0) g_off[N_NODES] = ETOT;
}

__global__ void k_place(const int* __restrict__ ei) {
    int i = (blockIdx.x * blockDim.x + threadIdx.x) * 4;
    if (i >= ETOT) return;
    int4 r4 = *(const int4*)(g_rank + i);
    if (i < N_EDGES) {
        int4 s4 = *(const int4*)(ei + i);
        int4 d4 = *(const int4*)(ei + N_EDGES + i);
        int o0 = g_off[d4.x], o1 = g_off[d4.y], o2 = g_off[d4.z], o3 = g_off[d4.w];
        g_psrc[o0 + r4.x] = s4.x;
        g_psrc[o1 + r4.y] = s4.y;
        g_psrc[o2 + r4.z] = s4.z;
        g_psrc[o3 + r4.w] = s4.w;
    } else {
        int d = i - N_EDGES;
        int o0 = g_off[d + 0], o1 = g_off[d + 1], o2 = g_off[d + 2], o3 = g_off[d + 3];
        g_psrc[o0 + r4.x] = d + 0;
        g_psrc[o1 + r4.y] = d + 1;
        g_psrc[o2 + r4.z] = d + 2;
        g_psrc[o3 + r4.w] = d + 3;
    }
}

// ---------------- wmma GEMM, 8 warps, register prefetch ----------------------
// h[M,128] = A[M,K] @ B[K,128] fp16 (fp32 acc); warp w: rows (w>>1)*16, cols (w&1)*64.
#define BM 64
#define BN 128
#define BK 32
#define LDA 40
#define LDB 136
#define LDC 136

__global__ __launch_bounds__(256, 2)
void k_gemm(const float* __restrict__ A32, const float* __restrict__ B,
            const float* __restrict__ att_s, const float* __restrict__ att_d,
            int M, int K) {
    __shared__ char smem_raw[BM * LDC * 4];                // 34816 B
    __half* As = (__half*)smem_raw;                        // [BM][LDA]
    __half* Bs = (__half*)(smem_raw + BM * LDA * 2);       // [BK][LDB]
    float*  Cs = (float*)smem_raw;                         // [BM][LDC] (epilogue)

    int tid  = threadIdx.x;
    int warp = tid >> 5;
    int m0   = blockIdx.x * BM;
    int wr   = (warp >> 1) * 16;   // warp row strip
    int wc   = (warp & 1) * 64;    // warp col half

    // load mappings
    int ar = tid >> 2, ac = (tid & 3) * 8;    // A: row 0..63, 8-col seg
    int br = tid >> 3, bc = (tid & 7) * 16;   // B: row 0..31, 16-col seg

    wmma::fragment<wmma::accumulator, 16, 16, 16, float> c[4];
    #pragma unroll
    for (int n = 0; n < 4; n++) wmma::fill_fragment(c[n], 0.0f);

    __half ha[8], hb[16];

    // ---- prologue fetch (k0 = 0)
    {
        int gm = m0 + ar;
        if (gm < M) {
            if (A32) {
                const float* src = A32 + (size_t)gm * K + ac;
                float4 f0 = *(const float4*)src;
                float4 f1 = *(const float4*)(src + 4);
                ha[0]=__float2half_rn(f0.x); ha[1]=__float2half_rn(f0.y);
                ha[2]=__float2half_rn(f0.z); ha[3]=__float2half_rn(f0.w);
                ha[4]=__float2half_rn(f1.x); ha[5]=__float2half_rn(f1.y);
                ha[6]=__float2half_rn(f1.z); ha[7]=__float2half_rn(f1.w);
            } else {
                *(uint4*)ha = *(const uint4*)(g_hn16 + (size_t)gm * K + ac);
            }
        } else {
            #pragma unroll
            for (int q = 0; q < 8; q++) ha[q] = __float2half_rn(0.f);
        }
        const float* srcb = B + (size_t)br * BN + bc;
        #pragma unroll
        for (int q = 0; q < 4; q++) {
            float4 f = *(const float4*)(srcb + q * 4);
            hb[q*4+0]=__float2half_rn(f.x); hb[q*4+1]=__float2half_rn(f.y);
            hb[q*4+2]=__float2half_rn(f.z); hb[q*4+3]=__float2half_rn(f.w);
        }
    }

    for (int k0 = 0; k0 < K; k0 += BK) {
        // store prefetched tiles
        *(uint4*)(As + ar * LDA + ac) = *(const uint4*)ha;
        *(uint4*)(Bs + br * LDB + bc)     = *(const uint4*)hb;
        *(uint4*)(Bs + br * LDB + bc + 8) = *(const uint4*)(hb + 8);
        __syncthreads();

        // prefetch next tiles into registers
        int kn = k0 + BK;
        if (kn < K) {
            int gm = m0 + ar;
            if (gm < M) {
                if (A32) {
                    const float* src = A32 + (size_t)gm * K + kn + ac;
                    float4 f0 = *(const float4*)src;
                    float4 f1 = *(const float4*)(src + 4);
                    ha[0]=__float2half_rn(f0.x); ha[1]=__float2half_rn(f0.y);
                    ha[2]=__float2half_rn(f0.z); ha[3]=__float2half_rn(f0.w);
                    ha[4]=__float2half_rn(f1.x); ha[5]=__float2half_rn(f1.y);
                    ha[6]=__float2half_rn(f1.z); ha[7]=__float2half_rn(f1.w);
                } else {
                    *(uint4*)ha = *(const uint4*)(g_hn16 + (size_t)gm * K + kn + ac);
                }
            } else {
                #pragma unroll
                for (int q = 0; q < 8; q++) ha[q] = __float2half_rn(0.f);
            }
            const float* srcb = B + (size_t)(kn + br) * BN + bc;
            #pragma unroll
            for (int q = 0; q < 4; q++) {
                float4 f = *(const float4*)(srcb + q * 4);
                hb[q*4+0]=__float2half_rn(f.x); hb[q*4+1]=__float2half_rn(f.y);
                hb[q*4+2]=__float2half_rn(f.z); hb[q*4+3]=__float2half_rn(f.w);
            }
        }

        // MMA: warp strip 16 rows x 64 cols, two k-subtiles
        #pragma unroll
        for (int ks = 0; ks < BK; ks += 16) {
            wmma::fragment<wmma::matrix_a, 16, 16, 16, __half, wmma::row_major> a;
            wmma::load_matrix_sync(a, As + wr * LDA + ks, LDA);
            #pragma unroll
            for (int n = 0; n < 4; n++) {
                wmma::fragment<wmma::matrix_b, 16, 16, 16, __half, wmma::row_major> bfr;
                wmma::load_matrix_sync(bfr, Bs + ks * LDB + wc + n * 16, LDB);
                wmma::mma_sync(c[n], a, bfr, c[n]);
            }
        }
        __syncthreads();
    }

    // ---- epilogue: frags -> smem fp32, fuse att dots + fp16 store
    #pragma unroll
    for (int n = 0; n < 4; n++)
        wmma::store_matrix_sync(Cs + wr * LDC + wc + n * 16, c[n], LDC,
                                wmma::mem_row_major);
    __syncthreads();

    {
        int r  = tid >> 2;            // 0..63
        int qd = tid & 3;             // col quarter: qd*32
        int gm = m0 + r;
        const float* crow = Cs + r * LDC + qd * 32;
        float ps = 0.f, pd = 0.f;
        __half hv[32];
        #pragma unroll
        for (int q = 0; q < 32; q += 4) {
            float4 f = *(const float4*)(crow + q);
            int col = qd * 32 + q;
            ps += f.x * att_s[col]     + f.y * att_s[col + 1]
                + f.z * att_s[col + 2] + f.w * att_s[col + 3];
            pd += f.x * att_d[col]     + f.y * att_d[col + 1]
                + f.z * att_d[col + 2] + f.w * att_d[col + 3];
            hv[q + 0] = __float2half_rn(f.x);
            hv[q + 1] = __float2half_rn(f.y);
            hv[q + 2] = __float2half_rn(f.z);
            hv[q + 3] = __float2half_rn(f.w);
        }
        // reduce across the 4 threads sharing row r (aligned 4-groups in warp)
        ps += __shfl_xor_sync(0xffffffffu, ps, 1);
        pd += __shfl_xor_sync(0xffffffffu, pd, 1);
        ps += __shfl_xor_sync(0xffffffffu, ps, 2);
        pd += __shfl_xor_sync(0xffffffffu, pd, 2);
        if (gm < M) {
            __half* dst = g_h16 + (size_t)gm * H + qd * 32;
            #pragma unroll
            for (int q = 0; q < 4; q++)
                *(uint4*)(dst + q * 8) = *(const uint4*)(hv + q * 8);
            if (qd == 0) { g_as[gm] = ps; g_ad[gm] = pd; }
        }
    }
}

// ---------------- aggregation: warp per dst node, fp16 gather, unroll 8 ------
__device__ __forceinline__ float lrexp(float e) {
    e = e > 0.f ? e : NEG_SLOPE * e;
    return __expf(e);
}

__device__ __forceinline__ float4 h16_load(int a, int lane) {
    uint2 v = *(const uint2*)(g_h16 + (size_t)a * H + lane * 4);
    float2 f0 = __half22float2(*(const __half2*)&v.x);
    float2 f1 = __half22float2(*(const __half2*)&v.y);
    return make_float4(f0.x, f0.y, f1.x, f1.y);
}

template<bool TAIL>
__global__ void k_agg(const float* __restrict__ bias,
                      const float* __restrict__ Wr, const float* __restrict__ br,
                      const float* __restrict__ Wc, const float* __restrict__ bc,
                      float* __restrict__ out) {
    int warp = threadIdx.x >> 5;
    int lane = threadIdx.x & 31;
    int n = blockIdx.x * 4 + warp;
    __shared__ float s0s[4], s1s[4];

    int s = g_off[n], e = g_off[n + 1];
    float ad = g_ad[n];
    float4 acc = make_float4(0.f, 0.f, 0.f, 0.f);
    float z = 0.f;

    int p = s;
    for (; p + 8 <= e; p += 8) {
        int idx[8];
        #pragma unroll
        for (int q = 0; q < 8; q++) idx[q] = __ldg(&g_psrc[p + q]);
        float w[8];
        #pragma unroll
        for (int q = 0; q < 8; q++) w[q] = lrexp(g_as[idx[q]] + ad);
        float4 hv[8];
        #pragma unroll
        for (int q = 0; q < 8; q++) hv[q] = h16_load(idx[q], lane);
        #pragma unroll
        for (int q = 0; q < 8; q++) {
            z += w[q];
            acc.x += w[q] * hv[q].x;
            acc.y += w[q] * hv[q].y;
            acc.z += w[q] * hv[q].z;
            acc.w += w[q] * hv[q].w;
        }
    }
    for (; p < e; p++) {
        int a0 = __ldg(&g_psrc[p]);
        float w0 = lrexp(g_as[a0] + ad);
        float4 h0 = h16_load(a0, lane);
        z += w0;
        acc.x += w0 * h0.x; acc.y += w0 * h0.y;
        acc.z += w0 * h0.z; acc.w += w0 * h0.w;
    }

    float inv = 1.0f / z;
    float4 b4 = ((const float4*)bias)[lane];
    float4 v;
    v.x = fmaxf(acc.x * inv + b4.x, 0.f);
    v.y = fmaxf(acc.y * inv + b4.y, 0.f);
    v.z = fmaxf(acc.z * inv + b4.z, 0.f);
    v.w = fmaxf(acc.w * inv + b4.w, 0.f);

    if (!TAIL) {
        __half2 hp[2];
        hp[0] = __floats2half2_rn(v.x, v.y);
        hp[1] = __floats2half2_rn(v.z, v.w);
        *(uint2*)(g_hn16 + (size_t)n * H + lane * 4) = *(const uint2*)hp;
    } else {
        float4 wr = ((const float4*)Wr)[lane];
        float dot = v.x * wr.x + v.y * wr.y + v.z * wr.z + v.w * wr.w;
        #pragma unroll
        for (int o = 16; o; o >>= 1) dot += __shfl_down_sync(0xffffffffu, dot, o);
        if (lane == 0) {
            float r = dot + br[0];
            s0s[warp] = r * Wc[n * 2 + 0];
            s1s[warp] = r * Wc[n * 2 + 1];
        }
        __syncthreads();
        if (threadIdx.x == 0) {
            atomicAdd(&g_acc2[0], s0s[0] + s0s[1] + s0s[2] + s0s[3]);
            atomicAdd(&g_acc2[1], s1s[0] + s1s[1] + s1s[2] + s1s[3]);
            __threadfence();
            int old = atomicAdd(&g_done, 1);
            if (old == gridDim.x - 1) {
                g_done = 0;                              // restore invariants
                float r0 = atomicAdd(&g_acc2[0], 0.0f);
                float r1 = atomicAdd(&g_acc2[1], 0.0f);
                g_acc2[0] = 0.0f;
                g_acc2[1] = 0.0f;
                out[0] = r0 + bc[0];
                out[1] = r1 + bc[1];
            }
        }
    }
}

// ---------------- launch -------------------------------------------------------
extern "C" void kernel_launch(void* const* d_in, const int* in_sizes, int n_in,
                              void* d_out, int out_size) {
    const float* x   = (const float*)d_in[0];
    const int*   ei  = (const int*)  d_in[1];
    const float* W1  = (const float*)d_in[2];
    const float* as1 = (const float*)d_in[3];
    const float* ad1 = (const float*)d_in[4];
    const float* b1  = (const float*)d_in[5];
    const float* W2  = (const float*)d_in[6];
    const float* as2 = (const float*)d_in[7];
    const float* ad2 = (const float*)d_in[8];
    const float* b2  = (const float*)d_in[9];
    const float* Wr  = (const float*)d_in[10];
    const float* br  = (const float*)d_in[11];
    const float* Wc  = (const float*)d_in[12];
    const float* bc  = (const float*)d_in[13];
    float* out = (float*)d_out;

    // side stream + events for CSR ∥ GEMM1 overlap (handles created once)
    static cudaStream_t s1 = nullptr;
    static cudaEvent_t ev0 = nullptr, ev1 = nullptr;
    if (s1 == nullptr) {
        cudaStreamCreateWithFlags(&s1, cudaStreamNonBlocking);
        cudaEventCreateWithFlags(&ev0, cudaEventDisableTiming);
        cudaEventCreateWithFlags(&ev1, cudaEventDisableTiming);
    }

    // fork: CSR build on s1
    cudaEventRecord(ev0, 0);
    cudaStreamWaitEvent(s1, ev0, 0);
    k_hist <<<(ETOT / 4 + 255) / 256, 256, 0, s1>>>(ei);
    k_scan <<<1, 1024, 0, s1>>>();
    k_place<<<(ETOT / 4 + 255) / 256, 256, 0, s1>>>(ei);
    cudaEventRecord(ev1, s1);

    int gemm_grid = (N_NODES + BM - 1) / BM;

    // GEMM1 on main stream, concurrent with CSR build
    k_gemm<<<gemm_grid, 256>>>(x, W1, as1, ad1, N_NODES, F_IN);

    // join
    cudaStreamWaitEvent(0, ev1, 0);

    k_agg<false><<<N_NODES / 4, 128>>>(b1, nullptr, nullptr, nullptr, nullptr, nullptr);

    k_gemm<<<gemm_grid, 256>>>(nullptr, W2, as2, ad2, N_NODES, H);
    k_agg<true><<<N_NODES / 4, 128>>>(b2, Wr, br, Wc, bc, out);
}